// round 4
// baseline (speedup 1.0000x reference)
#include <cuda_runtime.h>
#include <math.h>

typedef unsigned long long ull;
typedef unsigned int u32;

#define B_   64
#define H_   1024
#define I_   512
#define L_   4
#define S_   512
#define H4   4096
#define KT   32
#define NCTA 128     // 4 layers * 32 CTAs
#define NTHR 256

// Hidden state double-buffered by wave parity: [parity][layer][row*H + col]
__device__ float g_h[2][L_][B_ * H_];
__device__ unsigned g_bar_count;
__device__ volatile unsigned g_bar_gen;

__device__ __forceinline__ ull bcast2(float v) {
    ull r; asm("mov.b64 %0, {%1, %1};" : "=l"(r) : "f"(v)); return r;
}
__device__ __forceinline__ void fma2(ull& d, ull a, ull b) {
    asm("fma.rn.f32x2 %0, %1, %2, %0;" : "+l"(d) : "l"(a), "l"(b));
}
__device__ __forceinline__ float2 u2f(ull v) {
    float2 f; asm("mov.b64 {%0, %1}, %2;" : "=f"(f.x), "=f"(f.y) : "l"(v)); return f;
}
__device__ __forceinline__ u32 sm_u32(const void* p) {
    u32 a;
    asm("{.reg .u64 t; cvta.to.shared.u64 t, %1; cvt.u32.u64 %0, t;}" : "=r"(a) : "l"(p));
    return a;
}

__device__ __forceinline__ void grid_sync() {
    __syncthreads();
    if (threadIdx.x == 0) {
        __threadfence();
        unsigned gen = g_bar_gen;
        if (atomicAdd(&g_bar_count, 1u) == NCTA - 1u) {
            g_bar_count = 0;
            __threadfence();
            g_bar_gen = gen + 1u;
        } else {
            while (g_bar_gen == gen) __nanosleep(64);
        }
        __threadfence();
    }
    __syncthreads();
}

// Issue cp.async for one weight tile: 32 k-rows x 128 z-cols (4 gates x 32 hcols)
// into smem layout [kk][lane] = float4{g0,g1,g2,g3}. 16 x 4B cp.async per thread.
__device__ __forceinline__ void issue_w(const float* __restrict__ Wk0, int hc0,
                                        u32 dst, int lane, int r) {
    #pragma unroll
    for (int j = 0; j < 4; j++) {
        const int kk = r + 8 * j;
        const float* s = Wk0 + (size_t)kk * H4 + hc0 + lane;
        const u32 d = dst + (u32)((kk * 32 + lane) * 16);
        #pragma unroll
        for (int g = 0; g < 4; g++)
            asm volatile("cp.async.ca.shared.global [%0], [%1], 4;"
                         :: "r"(d + 4u * g), "l"(s + 1024 * g));
    }
}

// Register prefetch of one input tile: thread owns k-col (k0+lane), rows r*8..r*8+7.
__device__ __forceinline__ void ldg_inp(const float* __restrict__ inp, int ldi, int k0,
                                        int lane, int r, float pa[8]) {
    #pragma unroll
    for (int j = 0; j < 8; j++)
        pa[j] = __ldcg(inp + (size_t)(r * 8 + j) * ldi + k0 + lane);
}

// Conflict-free staging: 2x STS.128 per thread. smem row index = lane (= k within
// tile), 16 groups of 4 rows, group position XOR-swizzled by (lane & 15).
__device__ __forceinline__ void sts_inp(float* __restrict__ buf, int lane, int r,
                                        const float pa[8]) {
    float4* p0 = reinterpret_cast<float4*>(buf + lane * 64 + (((2 * r)     ^ (lane & 15)) << 2));
    float4* p1 = reinterpret_cast<float4*>(buf + lane * 64 + (((2 * r + 1) ^ (lane & 15)) << 2));
    *p0 = make_float4(pa[0], pa[1], pa[2], pa[3]);
    *p1 = make_float4(pa[4], pa[5], pa[6], pa[7]);
}

__global__ void __launch_bounds__(NTHR, 1)
lstm_persist(const float* __restrict__ x,
             const float* __restrict__ Wx0, const float* __restrict__ Wh0,
             const float* __restrict__ b0,
             const float* __restrict__ Wxr, const float* __restrict__ Whr,
             const float* __restrict__ br,
             float* __restrict__ out)
{
    __shared__ __align__(16) float4 w_s[2][KT * 32];   // 32 KB
    __shared__ __align__(16) float  inp_s[2][KT * 64]; // 16 KB

    const int layer = blockIdx.x >> 5;
    const int hc0   = (blockIdx.x & 31) * 32;
    const int t     = threadIdx.x;
    const int lane  = t & 31;
    const int r     = t >> 5;
    const int r2    = 2 * r;
    const int hcol  = hc0 + lane;

    const float* WA   = (layer == 0) ? Wx0 : Wxr + (size_t)(layer - 1) * H_ * H4;
    const float* WB   = (layer == 0) ? Wh0 : Whr + (size_t)(layer - 1) * H_ * H4;
    const float* bias = (layer == 0) ? b0  : br + (size_t)(layer - 1) * H4;
    const int    KA   = (layer == 0) ? I_  : H_;
    const int    ntA  = KA / KT;
    const int    nt   = ntA + H_ / KT;

    const u32 wsm0 = sm_u32(&w_s[0][0]);
    const u32 wsm1 = sm_u32(&w_s[1][0]);

    float b4[4];
    #pragma unroll
    for (int g = 0; g < 4; g++)
        b4[g] = __ldg(bias + g * 1024 + hcol);

    float creg[8];
    #pragma unroll
    for (int i = 0; i < 8; i++) creg[i] = 0.f;

    const size_t HS = (size_t)S_ * B_ * H_;
    const size_t BH = (size_t)B_ * H_;

    for (int w = 0; w < S_ + L_ - 1; w++) {
        const int s = w - layer;
        if (s >= 0 && s < S_) {
            const int prPrev = (w & 1) ^ 1;
            const int prCur  = w & 1;

            const float* inA = (layer == 0) ? (x + (size_t)s * B_ * I_)
                                            : &g_h[prPrev][layer - 1][0];
            const int    ldA = (layer == 0) ? I_ : H_;
            const float* inB = &g_h[prPrev][layer][0];

            ull acc[4][4];
            #pragma unroll
            for (int p = 0; p < 4; p++)
                #pragma unroll
                for (int g = 0; g < 4; g++)
                    acc[p][g] = bcast2(b4[g]);

            // ---- fused GEMM over inA (ntA tiles) then inB (32 tiles) ----
            float pa[8];
            issue_w(WA, hc0, wsm0, lane, r);
            asm volatile("cp.async.commit_group;" ::: "memory");
            ldg_inp(inA, ldA, 0, lane, r, pa);
            sts_inp(&inp_s[0][0], lane, r, pa);
            asm volatile("cp.async.wait_group 0;" ::: "memory");
            __syncthreads();

            for (int tt = 0; tt < nt; tt++) {
                const int cur = tt & 1;
                const bool more = (tt + 1 < nt);
                if (more) {
                    const float* Wn; const float* ipn; int ldn, kn;
                    if (tt + 1 < ntA) {
                        Wn = WA + (size_t)(tt + 1) * KT * H4;
                        ipn = inA; ldn = ldA; kn = (tt + 1) * KT;
                    } else {
                        const int u = tt + 1 - ntA;
                        Wn = WB + (size_t)u * KT * H4;
                        ipn = inB; ldn = H_; kn = u * KT;
                    }
                    issue_w(Wn, hc0, cur ? wsm0 : wsm1, lane, r);
                    asm volatile("cp.async.commit_group;" ::: "memory");
                    ldg_inp(ipn, ldn, kn, lane, r, pa);
                }

                const float4* wp = &w_s[cur][lane];
                const float*  ib = &inp_s[cur][0];
                #pragma unroll
                for (int kk = 0; kk < KT; kk++) {
                    const float4 wv = wp[kk * 32];
                    const ull w0 = bcast2(wv.x), w1 = bcast2(wv.y);
                    const ull w2 = bcast2(wv.z), w3 = bcast2(wv.w);
                    const float* base = ib + kk * 64;
                    const ulonglong2 A0 = *reinterpret_cast<const ulonglong2*>(
                        base + ((r2 ^ (kk & 15)) << 2));
                    const ulonglong2 A1 = *reinterpret_cast<const ulonglong2*>(
                        base + (((r2 + 1) ^ (kk & 15)) << 2));
                    fma2(acc[0][0], A0.x, w0); fma2(acc[0][1], A0.x, w1);
                    fma2(acc[0][2], A0.x, w2); fma2(acc[0][3], A0.x, w3);
                    fma2(acc[1][0], A0.y, w0); fma2(acc[1][1], A0.y, w1);
                    fma2(acc[1][2], A0.y, w2); fma2(acc[1][3], A0.y, w3);
                    fma2(acc[2][0], A1.x, w0); fma2(acc[2][1], A1.x, w1);
                    fma2(acc[2][2], A1.x, w2); fma2(acc[2][3], A1.x, w3);
                    fma2(acc[3][0], A1.y, w0); fma2(acc[3][1], A1.y, w1);
                    fma2(acc[3][2], A1.y, w2); fma2(acc[3][3], A1.y, w3);
                }

                if (more) sts_inp(&inp_s[cur ^ 1][0], lane, r, pa);
                asm volatile("cp.async.wait_group 0;" ::: "memory");
                __syncthreads();
            }

            // ---- activations + state update ----
            float* hw = &g_h[prCur][layer][0];
            #pragma unroll
            for (int p = 0; p < 4; p++) {
                float2 zi = u2f(acc[p][0]);
                float2 zf = u2f(acc[p][1]);
                float2 zg = u2f(acc[p][2]);
                float2 zo = u2f(acc[p][3]);
                #pragma unroll
                for (int half = 0; half < 2; half++) {
                    const float vi = half ? zi.y : zi.x;
                    const float vf = half ? zf.y : zf.x;
                    const float vg = half ? zg.y : zg.x;
                    const float vo = half ? zo.y : zo.x;
                    const int rr  = p * 2 + half;
                    const int row = r * 8 + rr;
                    const float ig = 1.f / (1.f + expf(-vi));
                    const float fg = 1.f / (1.f + expf(-vf));
                    const float og = 1.f / (1.f + expf(-vo));
                    const float cn = fg * creg[rr] + ig * tanhf(vg);
                    const float hn = og * tanhf(cn);
                    creg[rr] = cn;
                    hw[row * H_ + hcol] = hn;
                    if (layer == L_ - 1)
                        out[(size_t)s * BH + row * H_ + hcol] = hn;
                    if (s == S_ - 1) {
                        out[HS + (size_t)layer * BH + row * H_ + hcol] = hn;
                        out[HS + (size_t)L_ * BH + (size_t)layer * BH + row * H_ + hcol] = cn;
                    }
                }
            }
        }
        if (w < S_ + L_ - 2) grid_sync();
    }
}

extern "C" void kernel_launch(void* const* d_in, const int* in_sizes, int n_in,
                              void* d_out, int out_size)
{
    const float* x   = (const float*)d_in[0];   // [512, 64, 512]
    const float* Wx0 = (const float*)d_in[1];   // [512, 4096]
    const float* Wh0 = (const float*)d_in[2];   // [1024, 4096]
    const float* b0  = (const float*)d_in[3];   // [4096]
    const float* Wxr = (const float*)d_in[4];   // [3, 1024, 4096]
    const float* Whr = (const float*)d_in[5];   // [3, 1024, 4096]
    const float* br  = (const float*)d_in[6];   // [3, 4096]
    float* out = (float*)d_out;

    void* hp;
    cudaGetSymbolAddress(&hp, g_h);
    cudaMemsetAsync(hp, 0, sizeof(float) * 2 * L_ * B_ * H_, 0);

    lstm_persist<<<NCTA, NTHR>>>(x, Wx0, Wh0, b0, Wxr, Whr, br, out);
}